// round 1
// baseline (speedup 1.0000x reference)
#include <cuda_runtime.h>
#include <cstdint>

#define D_MODEL 768
#define NHEAD   12
#define D_K     64
#define D_FF    3072
#define BATCH   2
#define SEQ     2048
#define ROWS    (BATCH*SEQ)   // 4096
#define EPS     1e-6f

// ---------------- scratch (device globals; no allocation allowed) ------------
__device__ float g_h   [ROWS*D_MODEL];
__device__ float g_q   [ROWS*D_MODEL];
__device__ float g_k   [ROWS*D_MODEL];
__device__ float g_v   [ROWS*D_MODEL];
__device__ float g_ctx [ROWS*D_MODEL];
__device__ float g_attn[ROWS*D_MODEL];
__device__ float g_h2  [ROWS*D_MODEL];
__device__ float g_ff  [ROWS*D_FF];

// ---------------- LayerNorm (torch semantics: unbiased var, eps on std) ------
__global__ __launch_bounds__(256) void ln_kernel(const float* __restrict__ x,
                                                 const float* __restrict__ gamma,
                                                 const float* __restrict__ beta,
                                                 float* __restrict__ out) {
    int row = blockIdx.x;
    const float* xr = x + (size_t)row * D_MODEL;
    float* orow     = out + (size_t)row * D_MODEL;
    __shared__ float red[32];
    __shared__ float s_mean, s_rdenom;
    int tid = threadIdx.x;

    float v0 = xr[tid], v1 = xr[tid + 256], v2 = xr[tid + 512];
    float s = v0 + v1 + v2;
    #pragma unroll
    for (int o = 16; o > 0; o >>= 1) s += __shfl_xor_sync(0xffffffffu, s, o);
    if ((tid & 31) == 0) red[tid >> 5] = s;
    __syncthreads();
    if (tid == 0) {
        float t = 0.f;
        #pragma unroll
        for (int i = 0; i < 8; i++) t += red[i];
        s_mean = t / (float)D_MODEL;
    }
    __syncthreads();
    float m = s_mean;
    float d0 = v0 - m, d1 = v1 - m, d2 = v2 - m;
    float sq = d0*d0 + d1*d1 + d2*d2;
    #pragma unroll
    for (int o = 16; o > 0; o >>= 1) sq += __shfl_xor_sync(0xffffffffu, sq, o);
    if ((tid & 31) == 0) red[tid >> 5] = sq;
    __syncthreads();
    if (tid == 0) {
        float t = 0.f;
        #pragma unroll
        for (int i = 0; i < 8; i++) t += red[i];
        float var = t / (float)(D_MODEL - 1);      // unbiased
        s_rdenom = 1.0f / (sqrtf(var) + EPS);      // eps added to std
    }
    __syncthreads();
    float r = s_rdenom;
    orow[tid      ] = gamma[tid      ] * (d0 * r) + beta[tid      ];
    orow[tid + 256] = gamma[tid + 256] * (d1 * r) + beta[tid + 256];
    orow[tid + 512] = gamma[tid + 512] * (d2 * r) + beta[tid + 512];
}

// ---------------- SGEMM: C[M,N] = A[M,K] @ B[K,N] + bias (+res) (+relu) ------
// BM=BN=128, BK=8, 256 threads, 8x8 per thread. All dims divide tiles exactly.
template<bool RELU>
__global__ __launch_bounds__(256) void gemm_kernel(const float* __restrict__ A,
                                                   const float* __restrict__ B,
                                                   const float* __restrict__ bias,
                                                   const float* __restrict__ residual,
                                                   float* __restrict__ C,
                                                   int M, int N, int K) {
    const int BM = 128, BN = 128, BK = 8, TM = 8, TN = 8;
    __shared__ float As[BK][BM];
    __shared__ float Bs[BK][BN];

    int tid = threadIdx.x;
    int bx = blockIdx.x, by = blockIdx.y;
    int tx = (tid % 16) * TN;
    int ty = (tid / 16) * TM;

    int a_row = tid >> 1;            // 0..127
    int a_col = (tid & 1) * 4;       // 0 or 4
    int b_row = tid >> 5;            // 0..7
    int b_col = (tid & 31) * 4;      // 0..124

    const float* Aptr = A + (size_t)(by * BM + a_row) * K + a_col;
    const float* Bptr = B + (size_t)b_row * N + bx * BN + b_col;

    float acc[TM][TN];
    #pragma unroll
    for (int i = 0; i < TM; i++)
        #pragma unroll
        for (int j = 0; j < TN; j++) acc[i][j] = 0.f;

    for (int k0 = 0; k0 < K; k0 += BK) {
        float4 av = *(const float4*)Aptr;
        As[a_col + 0][a_row] = av.x;
        As[a_col + 1][a_row] = av.y;
        As[a_col + 2][a_row] = av.z;
        As[a_col + 3][a_row] = av.w;
        *(float4*)(&Bs[b_row][b_col]) = *(const float4*)Bptr;
        __syncthreads();
        Aptr += BK;
        Bptr += (size_t)BK * N;
        #pragma unroll
        for (int kk = 0; kk < BK; kk++) {
            float ra[TM], rb[TN];
            #pragma unroll
            for (int i = 0; i < TM; i++) ra[i] = As[kk][ty + i];
            #pragma unroll
            for (int j = 0; j < TN; j++) rb[j] = Bs[kk][tx + j];
            #pragma unroll
            for (int i = 0; i < TM; i++)
                #pragma unroll
                for (int j = 0; j < TN; j++)
                    acc[i][j] += ra[i] * rb[j];
        }
        __syncthreads();
    }

    #pragma unroll
    for (int i = 0; i < TM; i++) {
        int row = by * BM + ty + i;
        #pragma unroll
        for (int j = 0; j < TN; j += 4) {
            int col = bx * BN + tx + j;
            float4 r = make_float4(acc[i][j], acc[i][j+1], acc[i][j+2], acc[i][j+3]);
            float4 bv = *(const float4*)(bias + col);
            r.x += bv.x; r.y += bv.y; r.z += bv.z; r.w += bv.w;
            if (RELU) {
                r.x = fmaxf(r.x, 0.f); r.y = fmaxf(r.y, 0.f);
                r.z = fmaxf(r.z, 0.f); r.w = fmaxf(r.w, 0.f);
            }
            if (residual) {
                float4 rr = *(const float4*)(residual + (size_t)row * N + col);
                r.x += rr.x; r.y += rr.y; r.z += rr.z; r.w += rr.w;
            }
            *(float4*)(C + (size_t)row * N + col) = r;
        }
    }
}

// ---------------- Flash attention (online softmax) ---------------------------
// grid (S/BQ, NHEAD, B), 64 threads, one query per thread.
#define BQ 64
#define BKT 64
__global__ __launch_bounds__(64) void attn_kernel(const float* __restrict__ q,
                                                  const float* __restrict__ k,
                                                  const float* __restrict__ v,
                                                  const int* __restrict__ mask,
                                                  float* __restrict__ ctx) {
    int qt = blockIdx.x, h = blockIdx.y, b = blockIdx.z;
    int tid = threadIdx.x;
    int qi  = qt * BQ + tid;

    __shared__ float Ks[BKT][D_K];
    __shared__ float Vs[BKT][D_K];
    __shared__ float Ss[BQ][BKT + 1];
    __shared__ int   Ms[BKT];

    const float* qrow = q + ((size_t)(b * SEQ + qi)) * D_MODEL + h * D_K;
    float qreg[D_K];
    #pragma unroll
    for (int d = 0; d < D_K; d++) qreg[d] = qrow[d] * 0.125f;  // 1/sqrt(64)

    float acc[D_K];
    #pragma unroll
    for (int d = 0; d < D_K; d++) acc[d] = 0.f;
    float m = -3.4e38f, l = 0.f;

    for (int kt = 0; kt < SEQ / BKT; kt++) {
        int kb = kt * BKT;
        __syncthreads();
        for (int i = tid; i < BKT * D_K; i += BQ) {
            int kk = i >> 6, d = i & 63;
            size_t gi = ((size_t)(b * SEQ + kb + kk)) * D_MODEL + h * D_K + d;
            Ks[kk][d] = k[gi];
            Vs[kk][d] = v[gi];
        }
        Ms[tid] = mask[b * SEQ + kb + tid];
        __syncthreads();

        float mt = m;
        #pragma unroll 4
        for (int kk = 0; kk < BKT; kk++) {
            float s = 0.f;
            #pragma unroll
            for (int d = 0; d < D_K; d++) s += qreg[d] * Ks[kk][d];
            if (Ms[kk] == 0) s = -1e9f;
            Ss[tid][kk] = s;
            mt = fmaxf(mt, s);
        }
        float scale = __expf(m - mt);
        m = mt;
        l *= scale;
        #pragma unroll
        for (int d = 0; d < D_K; d++) acc[d] *= scale;
        #pragma unroll 4
        for (int kk = 0; kk < BKT; kk++) {
            float p = __expf(Ss[tid][kk] - m);
            l += p;
            #pragma unroll
            for (int d = 0; d < D_K; d++) acc[d] += p * Vs[kk][d];
        }
    }
    float inv = 1.f / l;
    float* o = ctx + ((size_t)(b * SEQ + qi)) * D_MODEL + h * D_K;
    #pragma unroll
    for (int d = 0; d < D_K; d++) o[d] = acc[d] * inv;
}

// ---------------- driver ------------------------------------------------------
extern "C" void kernel_launch(void* const* d_in, const int* in_sizes, int n_in,
                              void* d_out, int out_size) {
    const float* x    = (const float*)d_in[0];
    const int*   mask = (const int*)  d_in[1];
    const float* Wq   = (const float*)d_in[2];
    const float* bq   = (const float*)d_in[3];
    const float* Wk   = (const float*)d_in[4];
    const float* bk   = (const float*)d_in[5];
    const float* Wv   = (const float*)d_in[6];
    const float* bv   = (const float*)d_in[7];
    const float* Wo   = (const float*)d_in[8];
    const float* bo   = (const float*)d_in[9];
    const float* ln1a = (const float*)d_in[10];
    const float* ln1b = (const float*)d_in[11];
    const float* W1   = (const float*)d_in[12];
    const float* b1   = (const float*)d_in[13];
    const float* W2   = (const float*)d_in[14];
    const float* b2   = (const float*)d_in[15];
    const float* ln2a = (const float*)d_in[16];
    const float* ln2b = (const float*)d_in[17];
    float* out = (float*)d_out;

    float *ph, *pq, *pk, *pv, *pctx, *pattn, *ph2, *pff;
    cudaGetSymbolAddress((void**)&ph,    g_h);
    cudaGetSymbolAddress((void**)&pq,    g_q);
    cudaGetSymbolAddress((void**)&pk,    g_k);
    cudaGetSymbolAddress((void**)&pv,    g_v);
    cudaGetSymbolAddress((void**)&pctx,  g_ctx);
    cudaGetSymbolAddress((void**)&pattn, g_attn);
    cudaGetSymbolAddress((void**)&ph2,   g_h2);
    cudaGetSymbolAddress((void**)&pff,   g_ff);

    // 1) h = LN1(x)
    ln_kernel<<<ROWS, 256>>>(x, ln1a, ln1b, ph);

    // 2) q,k,v = h @ W{q,k,v} + b
    dim3 g768(D_MODEL / 128, ROWS / 128);
    gemm_kernel<false><<<g768, 256>>>(ph, Wq, bq, nullptr, pq, ROWS, D_MODEL, D_MODEL);
    gemm_kernel<false><<<g768, 256>>>(ph, Wk, bk, nullptr, pk, ROWS, D_MODEL, D_MODEL);
    gemm_kernel<false><<<g768, 256>>>(ph, Wv, bv, nullptr, pv, ROWS, D_MODEL, D_MODEL);

    // 3) ctx = softmax(qk^T/sqrt(dk) masked) @ v
    dim3 ga(SEQ / BQ, NHEAD, BATCH);
    attn_kernel<<<ga, BQ>>>(pq, pk, pv, mask, pctx);

    // 4) attn_out = x + ctx @ Wo + bo
    gemm_kernel<false><<<g768, 256>>>(pctx, Wo, bo, x, pattn, ROWS, D_MODEL, D_MODEL);

    // 5) h2 = LN2(attn_out)
    ln_kernel<<<ROWS, 256>>>(pattn, ln2a, ln2b, ph2);

    // 6) ff = relu(h2 @ W1 + b1)
    dim3 gff(D_FF / 128, ROWS / 128);
    gemm_kernel<true><<<gff, 256>>>(ph2, W1, b1, nullptr, pff, ROWS, D_FF, D_MODEL);

    // 7) out = attn_out + ff @ W2 + b2
    gemm_kernel<false><<<g768, 256>>>(pff, W2, b2, pattn, out, ROWS, D_MODEL, D_FF);
}

// round 6
// speedup vs baseline: 1.6675x; 1.6675x over previous
#include <cuda_runtime.h>
#include <cstdint>

#define D_MODEL 768
#define NHEAD   12
#define D_K     64
#define D_FF    3072
#define BATCH   2
#define SEQ     2048
#define ROWS    (BATCH*SEQ)   // 4096
#define EPS     1e-6f
#define QKV_N   2304

// ---------------- scratch (device globals; no allocation allowed) ------------
__device__ float g_h    [ROWS*D_MODEL];
__device__ float g_qkv  [ROWS*QKV_N];
__device__ float g_ctx  [ROWS*D_MODEL];
__device__ float g_attn [ROWS*D_MODEL];
__device__ float g_h2   [ROWS*D_MODEL];
__device__ float g_ff   [ROWS*D_FF];
__device__ float g_wqkvT[QKV_N*D_MODEL];
__device__ float g_woT  [D_MODEL*D_MODEL];
__device__ float g_w1T  [D_FF*D_MODEL];
__device__ float g_w2T  [D_MODEL*D_FF];
__device__ float g_bqkv [QKV_N];

// ============================ helpers =========================================
__device__ __forceinline__ uint32_t smem_u32(const void* p) {
    uint32_t a;
    asm("{ .reg .u64 t; cvta.to.shared.u64 t, %1; cvt.u32.u64 %0, t; }" : "=r"(a) : "l"(p));
    return a;
}
__device__ __forceinline__ void cp16(uint32_t saddr, const float* g) {
    asm volatile("cp.async.cg.shared.global [%0], [%1], 16;"
                 :: "r"(saddr), "l"(__cvta_generic_to_global(g)));
}
__device__ __forceinline__ void cp_commit() {
    asm volatile("cp.async.commit_group;" ::: "memory");
}
__device__ __forceinline__ void cp_wait1() {
    asm volatile("cp.async.wait_group 1;" ::: "memory");
}
__device__ __forceinline__ float lds32f(uint32_t addr) {
    float v;
    asm volatile("ld.shared.f32 %0, [%1];" : "=f"(v) : "r"(addr));
    return v;
}
// 3xTF32 split: x = hi + lo (both tf32), lo*lo term dropped (~2^-22 rel).
__device__ __forceinline__ void tf32split(float x, uint32_t& hi, uint32_t& lo) {
    uint32_t h;
    asm("cvt.rna.tf32.f32 %0, %1;" : "=r"(h) : "f"(x));
    float r = x - __uint_as_float(h);
    uint32_t l;
    asm("cvt.rna.tf32.f32 %0, %1;" : "=r"(l) : "f"(r));
    hi = h; lo = l;
}
// m16n8k8 tf32 mma. Fragment layout (one tf32 per .b32, k4 atom x2):
//   a0={g,t} a1={g+8,t} a2={g,t+4} a3={g+8,t+4};  b0={k=t,n=g} b1={k=t+4,n=g}
//   c0={g,2t} c1={g,2t+1} c2={g+8,2t} c3={g+8,2t+1}
__device__ __forceinline__ void mma_tf32(float* c, const uint32_t* a, uint32_t b0, uint32_t b1) {
    asm volatile(
        "mma.sync.aligned.m16n8k8.row.col.f32.tf32.tf32.f32 "
        "{%0,%1,%2,%3}, {%4,%5,%6,%7}, {%8,%9}, {%0,%1,%2,%3};"
        : "+f"(c[0]), "+f"(c[1]), "+f"(c[2]), "+f"(c[3])
        : "r"(a[0]), "r"(a[1]), "r"(a[2]), "r"(a[3]), "r"(b0), "r"(b1));
}

// ============================ LayerNorm =======================================
__global__ __launch_bounds__(256) void ln_kernel(const float* __restrict__ x,
                                                 const float* __restrict__ gamma,
                                                 const float* __restrict__ beta,
                                                 float* __restrict__ out) {
    int row = blockIdx.x;
    const float* xr = x + (size_t)row * D_MODEL;
    float* orow     = out + (size_t)row * D_MODEL;
    __shared__ float red[32];
    __shared__ float s_mean, s_rdenom;
    int tid = threadIdx.x;

    float v0 = xr[tid], v1 = xr[tid + 256], v2 = xr[tid + 512];
    float s = v0 + v1 + v2;
    #pragma unroll
    for (int o = 16; o > 0; o >>= 1) s += __shfl_xor_sync(0xffffffffu, s, o);
    if ((tid & 31) == 0) red[tid >> 5] = s;
    __syncthreads();
    if (tid == 0) {
        float t = 0.f;
        #pragma unroll
        for (int i = 0; i < 8; i++) t += red[i];
        s_mean = t / (float)D_MODEL;
    }
    __syncthreads();
    float m = s_mean;
    float d0 = v0 - m, d1 = v1 - m, d2 = v2 - m;
    float sq = d0*d0 + d1*d1 + d2*d2;
    #pragma unroll
    for (int o = 16; o > 0; o >>= 1) sq += __shfl_xor_sync(0xffffffffu, sq, o);
    if ((tid & 31) == 0) red[tid >> 5] = sq;
    __syncthreads();
    if (tid == 0) {
        float t = 0.f;
        #pragma unroll
        for (int i = 0; i < 8; i++) t += red[i];
        float var = t / (float)(D_MODEL - 1);
        s_rdenom = 1.0f / (sqrtf(var) + EPS);
    }
    __syncthreads();
    float r = s_rdenom;
    orow[tid      ] = gamma[tid      ] * (d0 * r) + beta[tid      ];
    orow[tid + 256] = gamma[tid + 256] * (d1 * r) + beta[tid + 256];
    orow[tid + 512] = gamma[tid + 512] * (d2 * r) + beta[tid + 512];
}

// ============================ transpose / pack ================================
__global__ __launch_bounds__(256) void transpose_kernel(const float* __restrict__ src,
                                                        float* __restrict__ dst,
                                                        int R, int C) {
    __shared__ float t[32][33];
    int tx = threadIdx.x & 31, ty = threadIdx.x >> 5;
    int c0 = blockIdx.x * 32, r0 = blockIdx.y * 32;
    #pragma unroll
    for (int j = 0; j < 4; j++)
        t[ty + 8*j][tx] = src[(size_t)(r0 + ty + 8*j) * C + c0 + tx];
    __syncthreads();
    #pragma unroll
    for (int j = 0; j < 4; j++)
        dst[(size_t)(c0 + ty + 8*j) * R + r0 + tx] = t[tx][ty + 8*j];
}

__global__ void pack_bias_kernel(const float* __restrict__ bq, const float* __restrict__ bk,
                                 const float* __restrict__ bv, float* __restrict__ dst) {
    int i = blockIdx.x * 256 + threadIdx.x;
    if (i < 768) dst[i] = bq[i];
    else if (i < 1536) dst[i] = bk[i - 768];
    else if (i < QKV_N) dst[i] = bv[i - 1536];
}

// ============================ 3xTF32 mma.sync GEMM ============================
// C[M,N] = A[M,K] @ BT[N,K]^T (+bias)(+relu)(+res), fp32-accurate via 3xTF32.
// CTA tile 64 x 128, BK=32, 128 threads, 4 warps (2x2), warp tile 32 x 64.
// SMEM per stage: A 64*128B + B 128*128B = 24KB, double buffered (48KB).
// Swizzle: 16B chunk c of row r stored at chunk slot c^(r&7).
template<bool RELU, bool RES>
__global__ __launch_bounds__(128) void gemm_mma3(const float* __restrict__ A,
                                                 const float* __restrict__ BT,
                                                 const float* __restrict__ bias,
                                                 const float* __restrict__ res,
                                                 float* __restrict__ C,
                                                 int N, int K) {
    constexpr int BM = 64;
    constexpr int MT = 2;                 // 2 m-tiles of 16 rows per warp
    constexpr int A_BYTES = BM * 128;     // 8KB
    constexpr int B_BYTES = 128 * 128;    // 16KB
    constexpr int STAGE = A_BYTES + B_BYTES;

    extern __shared__ char smem[];
    uint32_t sbase = smem_u32(smem);
    int tid = threadIdx.x, wid = tid >> 5, lid = tid & 31;
    int g = lid >> 2, t = lid & 3;
    int wm = wid >> 1, wn = wid & 1;
    int bx = blockIdx.x, by = blockIdx.y;

    const float* Ab = A  + (size_t)by * BM * K;
    const float* Bb = BT + (size_t)bx * 128 * K;
    int NKT = K / 32;

    // ---- loader (cp.async 16B chunks, chunk c at row r lands at slot c^(r&7))
    int lr0 = tid >> 3;        // 0..15
    int lc  = tid & 7;         // 0..7
    auto load_tile = [&](int stage, int kt) {
        uint32_t aS = sbase + stage * STAGE;
        uint32_t bS = aS + A_BYTES;
        const float* Ak = Ab + kt * 32 + lc * 4;
        const float* Bk = Bb + kt * 32 + lc * 4;
        #pragma unroll
        for (int j = 0; j < 4; j++) {
            int r = lr0 + j * 16;
            cp16(aS + r * 128 + ((lc ^ (r & 7)) << 4), Ak + (size_t)r * K);
        }
        #pragma unroll
        for (int j = 0; j < 8; j++) {
            int r = lr0 + j * 16;
            cp16(bS + r * 128 + ((lc ^ (r & 7)) << 4), Bk + (size_t)r * K);
        }
        cp_commit();
    };

    float c[MT][8][4];
    #pragma unroll
    for (int i = 0; i < MT; i++)
        #pragma unroll
        for (int j = 0; j < 8; j++)
            #pragma unroll
            for (int q = 0; q < 4; q++) c[i][j][q] = 0.f;

    load_tile(0, 0);
    load_tile(1, 1);

    // row byte-bases (all rows for a given thread are ≡ g mod 8)
    int aRowG[MT], aRowG8[MT], bRowN[8];
    #pragma unroll
    for (int mt = 0; mt < MT; mt++) {
        int rg = wm * 32 + mt * 16 + g;
        aRowG[mt]  = rg * 128;
        aRowG8[mt] = (rg + 8) * 128;
    }
    #pragma unroll
    for (int nt = 0; nt < 8; nt++) bRowN[nt] = (wn * 64 + nt * 8 + g) * 128;

    for (int kt = 0; kt < NKT; kt++) {
        cp_wait1();
        __syncthreads();
        int s = kt & 1;
        uint32_t aS = sbase + s * STAGE;
        uint32_t bS = aS + A_BYTES;
        #pragma unroll
        for (int ks = 0; ks < 4; ks++) {
            // chunk 2ks holds cols 8ks..8ks+3 (a0/a1/b0 at elem offset t)
            // chunk 2ks+1 holds cols 8ks+4..8ks+7 (a2/a3/b1 at elem offset t)
            uint32_t o0 = (uint32_t)((((2 * ks)     ^ g) << 4) + 4 * t);
            uint32_t o1 = (uint32_t)((((2 * ks + 1) ^ g) << 4) + 4 * t);
            uint32_t ah[MT][4], al[MT][4];
            #pragma unroll
            for (int mt = 0; mt < MT; mt++) {
                tf32split(lds32f(aS + aRowG[mt]  + o0), ah[mt][0], al[mt][0]);
                tf32split(lds32f(aS + aRowG8[mt] + o0), ah[mt][1], al[mt][1]);
                tf32split(lds32f(aS + aRowG[mt]  + o1), ah[mt][2], al[mt][2]);
                tf32split(lds32f(aS + aRowG8[mt] + o1), ah[mt][3], al[mt][3]);
            }
            uint32_t bh0[8], bl0[8], bh1[8], bl1[8];
            #pragma unroll
            for (int nt = 0; nt < 8; nt++) {
                tf32split(lds32f(bS + bRowN[nt] + o0), bh0[nt], bl0[nt]);
                tf32split(lds32f(bS + bRowN[nt] + o1), bh1[nt], bl1[nt]);
            }
            #pragma unroll
            for (int mt = 0; mt < MT; mt++)
                #pragma unroll
                for (int nt = 0; nt < 8; nt++) {
                    mma_tf32(c[mt][nt], al[mt], bh0[nt], bh1[nt]);  // lo*hi
                    mma_tf32(c[mt][nt], ah[mt], bl0[nt], bl1[nt]);  // hi*lo
                    mma_tf32(c[mt][nt], ah[mt], bh0[nt], bh1[nt]);  // hi*hi
                }
        }
        __syncthreads();
        if (kt + 2 < NKT) load_tile(s, kt + 2);
    }

    // ---- epilogue: c0,c1 -> (row, col..col+1); c2,c3 -> (row+8, ...)
    #pragma unroll
    for (int mt = 0; mt < MT; mt++) {
        int row = by * BM + wm * 32 + mt * 16 + g;
        #pragma unroll
        for (int nt = 0; nt < 8; nt++) {
            int col = bx * 128 + wn * 64 + nt * 8 + 2 * t;
            float2 bv = *(const float2*)(bias + col);
            float2 v0, v1;
            v0.x = c[mt][nt][0] + bv.x; v0.y = c[mt][nt][1] + bv.y;
            v1.x = c[mt][nt][2] + bv.x; v1.y = c[mt][nt][3] + bv.y;
            if (RELU) {
                v0.x = fmaxf(v0.x, 0.f); v0.y = fmaxf(v0.y, 0.f);
                v1.x = fmaxf(v1.x, 0.f); v1.y = fmaxf(v1.y, 0.f);
            }
            if (RES) {
                float2 r0 = *(const float2*)(res + (size_t)row * N + col);
                float2 r1 = *(const float2*)(res + (size_t)(row + 8) * N + col);
                v0.x += r0.x; v0.y += r0.y;
                v1.x += r1.x; v1.y += r1.y;
            }
            *(float2*)(C + (size_t)row * N + col)       = v0;
            *(float2*)(C + (size_t)(row + 8) * N + col) = v1;
        }
    }
}

// ============================ attention =======================================
// grid (SEQ/64, NHEAD, BATCH), 64 threads, one query per thread, 32-key tiles.
#define AKT 32
__global__ __launch_bounds__(64) void attn_kernel(const float* __restrict__ qkv,
                                                  const int* __restrict__ mask,
                                                  float* __restrict__ ctx) {
    int qt = blockIdx.x, h = blockIdx.y, b = blockIdx.z;
    int tid = threadIdx.x;
    int qi  = qt * 64 + tid;

    __shared__ float Ks[AKT][D_K];
    __shared__ float Vs[AKT][D_K];
    __shared__ float Ss[64][AKT + 1];
    __shared__ int   Ms[AKT];

    const float* qrow = qkv + (size_t)(b * SEQ + qi) * QKV_N + h * D_K;
    float4 q4[16];
    #pragma unroll
    for (int i = 0; i < 16; i++) {
        float4 tq = *(const float4*)(qrow + i * 4);
        tq.x *= 0.125f; tq.y *= 0.125f; tq.z *= 0.125f; tq.w *= 0.125f;
        q4[i] = tq;
    }
    float4 a4[16];
    #pragma unroll
    for (int i = 0; i < 16; i++) a4[i] = make_float4(0.f, 0.f, 0.f, 0.f);
    float m = -3.4e38f, l = 0.f;

    const float* Kbase = qkv + (size_t)(b * SEQ) * QKV_N + 768  + h * D_K;
    const float* Vbase = qkv + (size_t)(b * SEQ) * QKV_N + 1536 + h * D_K;

    for (int kt = 0; kt < SEQ / AKT; kt++) {
        int kb = kt * AKT;
        __syncthreads();
        #pragma unroll
        for (int j = 0; j < 8; j++) {
            int i = tid + 64 * j;
            int r = i >> 4, cc = (i & 15) * 4;
            *(float4*)(&Ks[r][cc]) = *(const float4*)(Kbase + (size_t)(kb + r) * QKV_N + cc);
            *(float4*)(&Vs[r][cc]) = *(const float4*)(Vbase + (size_t)(kb + r) * QKV_N + cc);
        }
        if (tid < AKT) Ms[tid] = mask[b * SEQ + kb + tid];
        __syncthreads();

        float mt = m;
        #pragma unroll 4
        for (int kk = 0; kk < AKT; kk++) {
            const float4* k4 = (const float4*)Ks[kk];
            float s0 = 0.f, s1 = 0.f, s2 = 0.f, s3 = 0.f;
            #pragma unroll
            for (int i = 0; i < 16; i++) {
                float4 kv = k4[i];
                s0 += q4[i].x * kv.x; s1 += q4[i].y * kv.y;
                s2 += q4[i].z * kv.z; s3 += q4[i].w * kv.w;
            }
            float sv = (s0 + s1) + (s2 + s3);
            if (Ms[kk] == 0) sv = -1e9f;
            Ss[tid][kk] = sv;
            mt = fmaxf(mt, sv);
        }
        float scale = __expf(m - mt);
        m = mt;
        l *= scale;
        #pragma unroll
        for (int i = 0; i < 16; i++) {
            a4[i].x *= scale; a4[i].y *= scale; a4[i].z *= scale; a4[i].w *= scale;
        }
        #pragma unroll 4
        for (int kk = 0; kk < AKT; kk++) {
            float p = __expf(Ss[tid][kk] - m);
            l += p;
            const float4* v4 = (const float4*)Vs[kk];
            #pragma unroll
            for (int i = 0; i < 16; i++) {
                float4 vv = v4[i];
                a4[i].x += p * vv.x; a4[i].y += p * vv.y;
                a4[i].z += p * vv.z; a4[i].w += p * vv.w;
            }
        }
    }
    float inv = 1.f / l;
    float* o = ctx + (size_t)(b * SEQ + qi) * D_MODEL + h * D_K;
    #pragma unroll
    for (int i = 0; i < 16; i++) {
        float4 w = a4[i];
        w.x *= inv; w.y *= inv; w.z *= inv; w.w *= inv;
        *(float4*)(o + i * 4) = w;
    }
}

// ============================ driver ==========================================
#define GEMM_SMEM (2 * (64*128 + 128*128))   // 49152

extern "C" void kernel_launch(void* const* d_in, const int* in_sizes, int n_in,
                              void* d_out, int out_size) {
    const float* x    = (const float*)d_in[0];
    const int*   mask = (const int*)  d_in[1];
    const float* Wq   = (const float*)d_in[2];
    const float* bq   = (const float*)d_in[3];
    const float* Wk   = (const float*)d_in[4];
    const float* bk   = (const float*)d_in[5];
    const float* Wv   = (const float*)d_in[6];
    const float* bv   = (const float*)d_in[7];
    const float* Wo   = (const float*)d_in[8];
    const float* bo   = (const float*)d_in[9];
    const float* ln1a = (const float*)d_in[10];
    const float* ln1b = (const float*)d_in[11];
    const float* W1   = (const float*)d_in[12];
    const float* b1   = (const float*)d_in[13];
    const float* W2   = (const float*)d_in[14];
    const float* b2   = (const float*)d_in[15];
    const float* ln2a = (const float*)d_in[16];
    const float* ln2b = (const float*)d_in[17];
    float* out = (float*)d_out;

    float *ph, *pqkv, *pctx, *pattn, *ph2, *pff;
    float *pwqkvT, *pwoT, *pw1T, *pw2T, *pbqkv;
    cudaGetSymbolAddress((void**)&ph,     g_h);
    cudaGetSymbolAddress((void**)&pqkv,   g_qkv);
    cudaGetSymbolAddress((void**)&pctx,   g_ctx);
    cudaGetSymbolAddress((void**)&pattn,  g_attn);
    cudaGetSymbolAddress((void**)&ph2,    g_h2);
    cudaGetSymbolAddress((void**)&pff,    g_ff);
    cudaGetSymbolAddress((void**)&pwqkvT, g_wqkvT);
    cudaGetSymbolAddress((void**)&pwoT,   g_woT);
    cudaGetSymbolAddress((void**)&pw1T,   g_w1T);
    cudaGetSymbolAddress((void**)&pw2T,   g_w2T);
    cudaGetSymbolAddress((void**)&pbqkv,  g_bqkv);

    cudaFuncSetAttribute(gemm_mma3<false,false>, cudaFuncAttributeMaxDynamicSharedMemorySize, GEMM_SMEM);
    cudaFuncSetAttribute(gemm_mma3<true, false>, cudaFuncAttributeMaxDynamicSharedMemorySize, GEMM_SMEM);
    cudaFuncSetAttribute(gemm_mma3<false,true >, cudaFuncAttributeMaxDynamicSharedMemorySize, GEMM_SMEM);

    // 0) weight transposes + bias pack
    transpose_kernel<<<dim3(24, 24), 256>>>(Wq, pwqkvT,            768, 768);
    transpose_kernel<<<dim3(24, 24), 256>>>(Wk, pwqkvT + 768*768,  768, 768);
    transpose_kernel<<<dim3(24, 24), 256>>>(Wv, pwqkvT + 1536*768, 768, 768);
    transpose_kernel<<<dim3(24, 24), 256>>>(Wo, pwoT,              768, 768);
    transpose_kernel<<<dim3(96, 24), 256>>>(W1, pw1T,              768, 3072);
    transpose_kernel<<<dim3(24, 96), 256>>>(W2, pw2T,              3072, 768);
    pack_bias_kernel<<<9, 256>>>(bq, bk, bv, pbqkv);

    // 1) h = LN1(x)
    ln_kernel<<<ROWS, 256>>>(x, ln1a, ln1b, ph);

    // 2) qkv = h @ W_qkv + b_qkv   (fused, N=2304)
    gemm_mma3<false,false><<<dim3(QKV_N/128, ROWS/64), 128, GEMM_SMEM>>>(
        ph, pwqkvT, pbqkv, nullptr, pqkv, QKV_N, D_MODEL);

    // 3) ctx = attention(q, k, v)
    attn_kernel<<<dim3(SEQ/64, NHEAD, BATCH), 64>>>(pqkv, mask, pctx);

    // 4) attn_out = x + ctx @ Wo + bo
    gemm_mma3<false,true><<<dim3(D_MODEL/128, ROWS/64), 128, GEMM_SMEM>>>(
        pctx, pwoT, bo, x, pattn, D_MODEL, D_MODEL);

    // 5) h2 = LN2(attn_out)
    ln_kernel<<<ROWS, 256>>>(pattn, ln2a, ln2b, ph2);

    // 6) ff = relu(h2 @ W1 + b1)
    gemm_mma3<true,false><<<dim3(D_FF/128, ROWS/64), 128, GEMM_SMEM>>>(
        ph2, pw1T, b1, nullptr, pff, D_FF, D_MODEL);

    // 7) out = attn_out + ff @ W2 + b2
    gemm_mma3<false,true><<<dim3(D_MODEL/128, ROWS/64), 128, GEMM_SMEM>>>(
        pff, pw2T, b2, pattn, out, D_MODEL, D_FF);
}

// round 7
// speedup vs baseline: 1.8598x; 1.1153x over previous
#include <cuda_runtime.h>
#include <cstdint>

#define D_MODEL 768
#define NHEAD   12
#define D_K     64
#define D_FF    3072
#define BATCH   2
#define SEQ     2048
#define ROWS    (BATCH*SEQ)   // 4096
#define EPS     1e-6f
#define QKV_N   2304

// ---------------- scratch (device globals; no allocation allowed) ------------
__device__ float g_h    [ROWS*D_MODEL];
__device__ float g_qkv  [ROWS*QKV_N];
__device__ float g_ctx  [ROWS*D_MODEL];
__device__ float g_attn [ROWS*D_MODEL];
__device__ float g_h2   [ROWS*D_MODEL];
__device__ float g_ff   [ROWS*D_FF];
__device__ float g_wqkvT[QKV_N*D_MODEL];
__device__ float g_woT  [D_MODEL*D_MODEL];
__device__ float g_w1T  [D_FF*D_MODEL];
__device__ float g_w2T  [D_MODEL*D_FF];
__device__ float g_bqkv [QKV_N];

// ============================ helpers =========================================
__device__ __forceinline__ uint32_t smem_u32(const void* p) {
    uint32_t a;
    asm("{ .reg .u64 t; cvta.to.shared.u64 t, %1; cvt.u32.u64 %0, t; }" : "=r"(a) : "l"(p));
    return a;
}
__device__ __forceinline__ void cp16(uint32_t saddr, const float* g) {
    asm volatile("cp.async.cg.shared.global [%0], [%1], 16;"
                 :: "r"(saddr), "l"(__cvta_generic_to_global(g)));
}
__device__ __forceinline__ void cp_commit() {
    asm volatile("cp.async.commit_group;" ::: "memory");
}
__device__ __forceinline__ void cp_wait1() {
    asm volatile("cp.async.wait_group 1;" ::: "memory");
}
__device__ __forceinline__ float lds32f(uint32_t addr) {
    float v;
    asm volatile("ld.shared.f32 %0, [%1];" : "=f"(v) : "r"(addr));
    return v;
}
// 3xTF32 split: x = hi + lo (both tf32), lo*lo term dropped (~2^-22 rel).
__device__ __forceinline__ void tf32split(float x, uint32_t& hi, uint32_t& lo) {
    uint32_t h;
    asm("cvt.rna.tf32.f32 %0, %1;" : "=r"(h) : "f"(x));
    float r = x - __uint_as_float(h);
    uint32_t l;
    asm("cvt.rna.tf32.f32 %0, %1;" : "=r"(l) : "f"(r));
    hi = h; lo = l;
}
// m16n8k8 tf32 mma. Fragment layout (one tf32 per .b32, k4 atom x2):
//   a0={g,t} a1={g+8,t} a2={g,t+4} a3={g+8,t+4};  b0={k=t,n=g} b1={k=t+4,n=g}
//   c0={g,2t} c1={g,2t+1} c2={g+8,2t} c3={g+8,2t+1}
__device__ __forceinline__ void mma_tf32(float* c, const uint32_t* a, uint32_t b0, uint32_t b1) {
    asm volatile(
        "mma.sync.aligned.m16n8k8.row.col.f32.tf32.tf32.f32 "
        "{%0,%1,%2,%3}, {%4,%5,%6,%7}, {%8,%9}, {%0,%1,%2,%3};"
        : "+f"(c[0]), "+f"(c[1]), "+f"(c[2]), "+f"(c[3])
        : "r"(a[0]), "r"(a[1]), "r"(a[2]), "r"(a[3]), "r"(b0), "r"(b1));
}

// ============================ LayerNorm =======================================
__global__ __launch_bounds__(256) void ln_kernel(const float* __restrict__ x,
                                                 const float* __restrict__ gamma,
                                                 const float* __restrict__ beta,
                                                 float* __restrict__ out) {
    int row = blockIdx.x;
    const float* xr = x + (size_t)row * D_MODEL;
    float* orow     = out + (size_t)row * D_MODEL;
    __shared__ float red[32];
    __shared__ float s_mean, s_rdenom;
    int tid = threadIdx.x;

    float v0 = xr[tid], v1 = xr[tid + 256], v2 = xr[tid + 512];
    float s = v0 + v1 + v2;
    #pragma unroll
    for (int o = 16; o > 0; o >>= 1) s += __shfl_xor_sync(0xffffffffu, s, o);
    if ((tid & 31) == 0) red[tid >> 5] = s;
    __syncthreads();
    if (tid == 0) {
        float t = 0.f;
        #pragma unroll
        for (int i = 0; i < 8; i++) t += red[i];
        s_mean = t / (float)D_MODEL;
    }
    __syncthreads();
    float m = s_mean;
    float d0 = v0 - m, d1 = v1 - m, d2 = v2 - m;
    float sq = d0*d0 + d1*d1 + d2*d2;
    #pragma unroll
    for (int o = 16; o > 0; o >>= 1) sq += __shfl_xor_sync(0xffffffffu, sq, o);
    if ((tid & 31) == 0) red[tid >> 5] = sq;
    __syncthreads();
    if (tid == 0) {
        float t = 0.f;
        #pragma unroll
        for (int i = 0; i < 8; i++) t += red[i];
        float var = t / (float)(D_MODEL - 1);
        s_rdenom = 1.0f / (sqrtf(var) + EPS);
    }
    __syncthreads();
    float r = s_rdenom;
    orow[tid      ] = gamma[tid      ] * (d0 * r) + beta[tid      ];
    orow[tid + 256] = gamma[tid + 256] * (d1 * r) + beta[tid + 256];
    orow[tid + 512] = gamma[tid + 512] * (d2 * r) + beta[tid + 512];
}

// ============================ transpose / pack ================================
__global__ __launch_bounds__(256) void transpose_kernel(const float* __restrict__ src,
                                                        float* __restrict__ dst,
                                                        int R, int C) {
    __shared__ float t[32][33];
    int tx = threadIdx.x & 31, ty = threadIdx.x >> 5;
    int c0 = blockIdx.x * 32, r0 = blockIdx.y * 32;
    #pragma unroll
    for (int j = 0; j < 4; j++)
        t[ty + 8*j][tx] = src[(size_t)(r0 + ty + 8*j) * C + c0 + tx];
    __syncthreads();
    #pragma unroll
    for (int j = 0; j < 4; j++)
        dst[(size_t)(c0 + ty + 8*j) * R + r0 + tx] = t[tx][ty + 8*j];
}

__global__ void pack_bias_kernel(const float* __restrict__ bq, const float* __restrict__ bk,
                                 const float* __restrict__ bv, float* __restrict__ dst) {
    int i = blockIdx.x * 256 + threadIdx.x;
    if (i < 768) dst[i] = bq[i];
    else if (i < 1536) dst[i] = bk[i - 768];
    else if (i < QKV_N) dst[i] = bv[i - 1536];
}

// ============================ 3xTF32 mma.sync GEMM ============================
// C[M,N] = A[M,K] @ BT[N,K]^T (+bias)(+relu)(+res), fp32-accurate via 3xTF32.
// CTA tile 64 x 128, BK=32, 128 threads, 4 warps (2x2), warp tile 32 x 64.
template<bool RELU, bool RES>
__global__ __launch_bounds__(128) void gemm_mma3(const float* __restrict__ A,
                                                 const float* __restrict__ BT,
                                                 const float* __restrict__ bias,
                                                 const float* __restrict__ res,
                                                 float* __restrict__ C,
                                                 int N, int K) {
    constexpr int BM = 64;
    constexpr int MT = 2;
    constexpr int A_BYTES = BM * 128;
    constexpr int B_BYTES = 128 * 128;
    constexpr int STAGE = A_BYTES + B_BYTES;

    extern __shared__ char smem[];
    uint32_t sbase = smem_u32(smem);
    int tid = threadIdx.x, wid = tid >> 5, lid = tid & 31;
    int g = lid >> 2, t = lid & 3;
    int wm = wid >> 1, wn = wid & 1;
    int bx = blockIdx.x, by = blockIdx.y;

    const float* Ab = A  + (size_t)by * BM * K;
    const float* Bb = BT + (size_t)bx * 128 * K;
    int NKT = K / 32;

    int lr0 = tid >> 3;
    int lc  = tid & 7;
    auto load_tile = [&](int stage, int kt) {
        uint32_t aS = sbase + stage * STAGE;
        uint32_t bS = aS + A_BYTES;
        const float* Ak = Ab + kt * 32 + lc * 4;
        const float* Bk = Bb + kt * 32 + lc * 4;
        #pragma unroll
        for (int j = 0; j < 4; j++) {
            int r = lr0 + j * 16;
            cp16(aS + r * 128 + ((lc ^ (r & 7)) << 4), Ak + (size_t)r * K);
        }
        #pragma unroll
        for (int j = 0; j < 8; j++) {
            int r = lr0 + j * 16;
            cp16(bS + r * 128 + ((lc ^ (r & 7)) << 4), Bk + (size_t)r * K);
        }
        cp_commit();
    };

    float c[MT][8][4];
    #pragma unroll
    for (int i = 0; i < MT; i++)
        #pragma unroll
        for (int j = 0; j < 8; j++)
            #pragma unroll
            for (int q = 0; q < 4; q++) c[i][j][q] = 0.f;

    load_tile(0, 0);
    load_tile(1, 1);

    int aRowG[MT], aRowG8[MT], bRowN[8];
    #pragma unroll
    for (int mt = 0; mt < MT; mt++) {
        int rg = wm * 32 + mt * 16 + g;
        aRowG[mt]  = rg * 128;
        aRowG8[mt] = (rg + 8) * 128;
    }
    #pragma unroll
    for (int nt = 0; nt < 8; nt++) bRowN[nt] = (wn * 64 + nt * 8 + g) * 128;

    for (int kt = 0; kt < NKT; kt++) {
        cp_wait1();
        __syncthreads();
        int s = kt & 1;
        uint32_t aS = sbase + s * STAGE;
        uint32_t bS = aS + A_BYTES;
        #pragma unroll
        for (int ks = 0; ks < 4; ks++) {
            uint32_t o0 = (uint32_t)((((2 * ks)     ^ g) << 4) + 4 * t);
            uint32_t o1 = (uint32_t)((((2 * ks + 1) ^ g) << 4) + 4 * t);
            uint32_t ah[MT][4], al[MT][4];
            #pragma unroll
            for (int mt = 0; mt < MT; mt++) {
                tf32split(lds32f(aS + aRowG[mt]  + o0), ah[mt][0], al[mt][0]);
                tf32split(lds32f(aS + aRowG8[mt] + o0), ah[mt][1], al[mt][1]);
                tf32split(lds32f(aS + aRowG[mt]  + o1), ah[mt][2], al[mt][2]);
                tf32split(lds32f(aS + aRowG8[mt] + o1), ah[mt][3], al[mt][3]);
            }
            uint32_t bh0[8], bl0[8], bh1[8], bl1[8];
            #pragma unroll
            for (int nt = 0; nt < 8; nt++) {
                tf32split(lds32f(bS + bRowN[nt] + o0), bh0[nt], bl0[nt]);
                tf32split(lds32f(bS + bRowN[nt] + o1), bh1[nt], bl1[nt]);
            }
            #pragma unroll
            for (int mt = 0; mt < MT; mt++)
                #pragma unroll
                for (int nt = 0; nt < 8; nt++) {
                    mma_tf32(c[mt][nt], al[mt], bh0[nt], bh1[nt]);
                    mma_tf32(c[mt][nt], ah[mt], bl0[nt], bl1[nt]);
                    mma_tf32(c[mt][nt], ah[mt], bh0[nt], bh1[nt]);
                }
        }
        __syncthreads();
        if (kt + 2 < NKT) load_tile(s, kt + 2);
    }

    #pragma unroll
    for (int mt = 0; mt < MT; mt++) {
        int row = by * BM + wm * 32 + mt * 16 + g;
        #pragma unroll
        for (int nt = 0; nt < 8; nt++) {
            int col = bx * 128 + wn * 64 + nt * 8 + 2 * t;
            float2 bv = *(const float2*)(bias + col);
            float2 v0, v1;
            v0.x = c[mt][nt][0] + bv.x; v0.y = c[mt][nt][1] + bv.y;
            v1.x = c[mt][nt][2] + bv.x; v1.y = c[mt][nt][3] + bv.y;
            if (RELU) {
                v0.x = fmaxf(v0.x, 0.f); v0.y = fmaxf(v0.y, 0.f);
                v1.x = fmaxf(v1.x, 0.f); v1.y = fmaxf(v1.y, 0.f);
            }
            if (RES) {
                float2 r0 = *(const float2*)(res + (size_t)row * N + col);
                float2 r1 = *(const float2*)(res + (size_t)(row + 8) * N + col);
                v0.x += r0.x; v0.y += r0.y;
                v1.x += r1.x; v1.y += r1.y;
            }
            *(float2*)(C + (size_t)row * N + col)       = v0;
            *(float2*)(C + (size_t)(row + 8) * N + col) = v1;
        }
    }
}

// ============================ MMA flash attention =============================
// One CTA per (64-query tile, head, batch). 128 threads = 4 warps; warp w owns
// query rows 16w..16w+15. Loops 64-key tiles: S=Q@K^T (3xTF32 mma), online
// softmax in registers, P->smem, O += P@V (3xTF32 mma, V transposed in smem).
// SMEM (floats, stride 68/row): Qs[64][68] Ks[64][68] Vt[64][68] U[64][68] Ms[64]
#define AST 68
#define ATT_SMEM ((4*64*AST)*4 + 64*4)
__global__ __launch_bounds__(128) void attn_mma(const float* __restrict__ qkv,
                                                const int* __restrict__ mask,
                                                float* __restrict__ ctx) {
    extern __shared__ float sm[];
    float* Qs = sm;                  // queries [q][d]
    float* Ks = sm + 64*AST;         // keys    [k][d]
    float* Vt = sm + 2*64*AST;       // V^T     [d][k]
    float* U  = sm + 3*64*AST;       // Vs [k][d] early / P [q][k] later
    int*   Ms = (int*)(sm + 4*64*AST);

    int tid = threadIdx.x, wid = tid >> 5, lid = tid & 31;
    int g = lid >> 2, t = lid & 3;
    int qt = blockIdx.x, h = blockIdx.y, b = blockIdx.z;

    // ---- load Q tile (scaled by 1/sqrt(dk)=0.125), coalesced float4
    const float* Qg = qkv + ((size_t)(b * SEQ + qt * 64)) * QKV_N + h * D_K;
    #pragma unroll
    for (int j = 0; j < 8; j++) {
        int i = tid + 128 * j;
        int r = i >> 4, c = (i & 15) * 4;
        float4 v = *(const float4*)(Qg + (size_t)r * QKV_N + c);
        float* d = Qs + r * AST + c;
        d[0] = v.x * 0.125f; d[1] = v.y * 0.125f; d[2] = v.z * 0.125f; d[3] = v.w * 0.125f;
    }
    __syncthreads();

    // ---- cache Q fragments (hi/lo) for all 8 k-steps
    uint32_t qh[8][4], ql[8][4];
    int r0 = wid * 16 + g;
    #pragma unroll
    for (int ks = 0; ks < 8; ks++) {
        tf32split(Qs[r0 * AST + 8 * ks + t],           qh[ks][0], ql[ks][0]);
        tf32split(Qs[(r0 + 8) * AST + 8 * ks + t],     qh[ks][1], ql[ks][1]);
        tf32split(Qs[r0 * AST + 8 * ks + t + 4],       qh[ks][2], ql[ks][2]);
        tf32split(Qs[(r0 + 8) * AST + 8 * ks + t + 4], qh[ks][3], ql[ks][3]);
    }

    float o[8][4];
    #pragma unroll
    for (int nt = 0; nt < 8; nt++)
        #pragma unroll
        for (int c = 0; c < 4; c++) o[nt][c] = 0.f;
    float m0 = -3.4e38f, m1 = -3.4e38f, l0 = 0.f, l1 = 0.f;

    const float* Kg0 = qkv + ((size_t)(b * SEQ)) * QKV_N + 768  + h * D_K;
    const float* Vg0 = qkv + ((size_t)(b * SEQ)) * QKV_N + 1536 + h * D_K;

    for (int kt = 0; kt < SEQ / 64; kt++) {
        __syncthreads();   // prior-iteration consumers of Ks/Vt/U done
        // ---- fill K tile + V staging (U as Vs[k][d]) + mask
        #pragma unroll
        for (int j = 0; j < 8; j++) {
            int i = tid + 128 * j;
            int r = i >> 4, c = (i & 15) * 4;
            size_t go = (size_t)(kt * 64 + r) * QKV_N + c;
            *(float4*)(Ks + r * AST + c) = *(const float4*)(Kg0 + go);
            *(float4*)(U  + r * AST + c) = *(const float4*)(Vg0 + go);
        }
        if (tid < 64) Ms[tid] = mask[b * SEQ + kt * 64 + tid];
        __syncthreads();
        // ---- transpose Vs -> Vt (conflict-free: lane owns key k)
        {
            int k = tid & 63, dh = (tid >> 6) * 32;
            #pragma unroll
            for (int j = 0; j < 32; j++) {
                int d = dh + j;
                Vt[d * AST + k] = U[k * AST + d];
            }
        }
        __syncthreads();

        // ---- S = Q @ K^T   (16 q-rows x 64 keys per warp)
        float s[8][4];
        #pragma unroll
        for (int nt = 0; nt < 8; nt++)
            #pragma unroll
            for (int c = 0; c < 4; c++) s[nt][c] = 0.f;
        #pragma unroll
        for (int ks = 0; ks < 8; ks++) {
            uint32_t bh0[8], bl0[8], bh1[8], bl1[8];
            #pragma unroll
            for (int nt = 0; nt < 8; nt++) {
                tf32split(Ks[(nt * 8 + g) * AST + 8 * ks + t],     bh0[nt], bl0[nt]);
                tf32split(Ks[(nt * 8 + g) * AST + 8 * ks + t + 4], bh1[nt], bl1[nt]);
            }
            #pragma unroll
            for (int nt = 0; nt < 8; nt++) {
                mma_tf32(s[nt], ql[ks], bh0[nt], bh1[nt]);
                mma_tf32(s[nt], qh[ks], bl0[nt], bl1[nt]);
                mma_tf32(s[nt], qh[ks], bh0[nt], bh1[nt]);
            }
        }
        // ---- mask
        #pragma unroll
        for (int nt = 0; nt < 8; nt++) {
            int k0 = nt * 8 + 2 * t;
            if (Ms[k0]     == 0) { s[nt][0] = -1e9f; s[nt][2] = -1e9f; }
            if (Ms[k0 + 1] == 0) { s[nt][1] = -1e9f; s[nt][3] = -1e9f; }
        }
        // ---- online softmax (rows r0, r0+8; cols spread over quad)
        float mx0 = -3.4e38f, mx1 = -3.4e38f;
        #pragma unroll
        for (int nt = 0; nt < 8; nt++) {
            mx0 = fmaxf(mx0, fmaxf(s[nt][0], s[nt][1]));
            mx1 = fmaxf(mx1, fmaxf(s[nt][2], s[nt][3]));
        }
        mx0 = fmaxf(mx0, __shfl_xor_sync(0xffffffffu, mx0, 1));
        mx0 = fmaxf(mx0, __shfl_xor_sync(0xffffffffu, mx0, 2));
        mx1 = fmaxf(mx1, __shfl_xor_sync(0xffffffffu, mx1, 1));
        mx1 = fmaxf(mx1, __shfl_xor_sync(0xffffffffu, mx1, 2));
        float mn0 = fmaxf(m0, mx0), mn1 = fmaxf(m1, mx1);
        float sc0 = __expf(m0 - mn0), sc1 = __expf(m1 - mn1);
        m0 = mn0; m1 = mn1;
        float sum0 = 0.f, sum1 = 0.f;
        #pragma unroll
        for (int nt = 0; nt < 8; nt++) {
            float p0 = __expf(s[nt][0] - m0);
            float p1 = __expf(s[nt][1] - m0);
            float p2 = __expf(s[nt][2] - m1);
            float p3 = __expf(s[nt][3] - m1);
            sum0 += p0 + p1; sum1 += p2 + p3;
            int cc = nt * 8 + 2 * t;
            *(float2*)(U + r0 * AST + cc)       = make_float2(p0, p1);
            *(float2*)(U + (r0 + 8) * AST + cc) = make_float2(p2, p3);
        }
        sum0 += __shfl_xor_sync(0xffffffffu, sum0, 1);
        sum0 += __shfl_xor_sync(0xffffffffu, sum0, 2);
        sum1 += __shfl_xor_sync(0xffffffffu, sum1, 1);
        sum1 += __shfl_xor_sync(0xffffffffu, sum1, 2);
        l0 = l0 * sc0 + sum0;
        l1 = l1 * sc1 + sum1;
        #pragma unroll
        for (int nt = 0; nt < 8; nt++) {
            o[nt][0] *= sc0; o[nt][1] *= sc0;
            o[nt][2] *= sc1; o[nt][3] *= sc1;
        }
        // ---- O += P @ V   (P rows are warp-local in U; Vt ready since sync)
        #pragma unroll
        for (int ks = 0; ks < 8; ks++) {
            uint32_t ah[4], al[4];
            tf32split(U[r0 * AST + 8 * ks + t],           ah[0], al[0]);
            tf32split(U[(r0 + 8) * AST + 8 * ks + t],     ah[1], al[1]);
            tf32split(U[r0 * AST + 8 * ks + t + 4],       ah[2], al[2]);
            tf32split(U[(r0 + 8) * AST + 8 * ks + t + 4], ah[3], al[3]);
            uint32_t bh0[8], bl0[8], bh1[8], bl1[8];
            #pragma unroll
            for (int nt = 0; nt < 8; nt++) {
                tf32split(Vt[(nt * 8 + g) * AST + 8 * ks + t],     bh0[nt], bl0[nt]);
                tf32split(Vt[(nt * 8 + g) * AST + 8 * ks + t + 4], bh1[nt], bl1[nt]);
            }
            #pragma unroll
            for (int nt = 0; nt < 8; nt++) {
                mma_tf32(o[nt], al, bh0[nt], bh1[nt]);
                mma_tf32(o[nt], ah, bl0[nt], bl1[nt]);
                mma_tf32(o[nt], ah, bh0[nt], bh1[nt]);
            }
        }
    }

    // ---- normalize + write ctx[b, q, h*64 + d]
    float inv0 = 1.f / l0, inv1 = 1.f / l1;
    float* Og = ctx + ((size_t)(b * SEQ + qt * 64 + r0)) * D_MODEL + h * D_K;
    #pragma unroll
    for (int nt = 0; nt < 8; nt++) {
        int cc = nt * 8 + 2 * t;
        *(float2*)(Og + cc)                      = make_float2(o[nt][0] * inv0, o[nt][1] * inv0);
        *(float2*)(Og + (size_t)8 * D_MODEL + cc) = make_float2(o[nt][2] * inv1, o[nt][3] * inv1);
    }
}

// ============================ driver ==========================================
#define GEMM_SMEM (2 * (64*128 + 128*128))   // 49152

extern "C" void kernel_launch(void* const* d_in, const int* in_sizes, int n_in,
                              void* d_out, int out_size) {
    const float* x    = (const float*)d_in[0];
    const int*   mask = (const int*)  d_in[1];
    const float* Wq   = (const float*)d_in[2];
    const float* bq   = (const float*)d_in[3];
    const float* Wk   = (const float*)d_in[4];
    const float* bk   = (const float*)d_in[5];
    const float* Wv   = (const float*)d_in[6];
    const float* bv   = (const float*)d_in[7];
    const float* Wo   = (const float*)d_in[8];
    const float* bo   = (const float*)d_in[9];
    const float* ln1a = (const float*)d_in[10];
    const float* ln1b = (const float*)d_in[11];
    const float* W1   = (const float*)d_in[12];
    const float* b1   = (const float*)d_in[13];
    const float* W2   = (const float*)d_in[14];
    const float* b2   = (const float*)d_in[15];
    const float* ln2a = (const float*)d_in[16];
    const float* ln2b = (const float*)d_in[17];
    float* out = (float*)d_out;

    float *ph, *pqkv, *pctx, *pattn, *ph2, *pff;
    float *pwqkvT, *pwoT, *pw1T, *pw2T, *pbqkv;
    cudaGetSymbolAddress((void**)&ph,     g_h);
    cudaGetSymbolAddress((void**)&pqkv,   g_qkv);
    cudaGetSymbolAddress((void**)&pctx,   g_ctx);
    cudaGetSymbolAddress((void**)&pattn,  g_attn);
    cudaGetSymbolAddress((void**)&ph2,    g_h2);
    cudaGetSymbolAddress((void**)&pff,    g_ff);
    cudaGetSymbolAddress((void**)&pwqkvT, g_wqkvT);
    cudaGetSymbolAddress((void**)&pwoT,   g_woT);
    cudaGetSymbolAddress((void**)&pw1T,   g_w1T);
    cudaGetSymbolAddress((void**)&pw2T,   g_w2T);
    cudaGetSymbolAddress((void**)&pbqkv,  g_bqkv);

    cudaFuncSetAttribute(gemm_mma3<false,false>, cudaFuncAttributeMaxDynamicSharedMemorySize, GEMM_SMEM);
    cudaFuncSetAttribute(gemm_mma3<true, false>, cudaFuncAttributeMaxDynamicSharedMemorySize, GEMM_SMEM);
    cudaFuncSetAttribute(gemm_mma3<false,true >, cudaFuncAttributeMaxDynamicSharedMemorySize, GEMM_SMEM);
    cudaFuncSetAttribute(attn_mma, cudaFuncAttributeMaxDynamicSharedMemorySize, ATT_SMEM);

    // 0) weight transposes + bias pack
    transpose_kernel<<<dim3(24, 24), 256>>>(Wq, pwqkvT,            768, 768);
    transpose_kernel<<<dim3(24, 24), 256>>>(Wk, pwqkvT + 768*768,  768, 768);
    transpose_kernel<<<dim3(24, 24), 256>>>(Wv, pwqkvT + 1536*768, 768, 768);
    transpose_kernel<<<dim3(24, 24), 256>>>(Wo, pwoT,              768, 768);
    transpose_kernel<<<dim3(96, 24), 256>>>(W1, pw1T,              768, 3072);
    transpose_kernel<<<dim3(24, 96), 256>>>(W2, pw2T,              3072, 768);
    pack_bias_kernel<<<9, 256>>>(bq, bk, bv, pbqkv);

    // 1) h = LN1(x)
    ln_kernel<<<ROWS, 256>>>(x, ln1a, ln1b, ph);

    // 2) qkv = h @ W_qkv + b_qkv   (fused, N=2304)
    gemm_mma3<false,false><<<dim3(QKV_N/128, ROWS/64), 128, GEMM_SMEM>>>(
        ph, pwqkvT, pbqkv, nullptr, pqkv, QKV_N, D_MODEL);

    // 3) ctx = attention(q, k, v)  (tensor-core flash)
    attn_mma<<<dim3(SEQ/64, NHEAD, BATCH), 128, ATT_SMEM>>>(pqkv, mask, pctx);

    // 4) attn_out = x + ctx @ Wo + bo
    gemm_mma3<false,true><<<dim3(D_MODEL/128, ROWS/64), 128, GEMM_SMEM>>>(
        pctx, pwoT, bo, x, pattn, D_MODEL, D_MODEL);

    // 5) h2 = LN2(attn_out)
    ln_kernel<<<ROWS, 256>>>(pattn, ln2a, ln2b, ph2);

    // 6) ff = relu(h2 @ W1 + b1)
    gemm_mma3<true,false><<<dim3(D_FF/128, ROWS/64), 128, GEMM_SMEM>>>(
        ph2, pw1T, b1, nullptr, pff, D_FF, D_MODEL);

    // 7) out = attn_out + ff @ W2 + b2
    gemm_mma3<false,true><<<dim3(D_MODEL/128, ROWS/64), 128, GEMM_SMEM>>>(
        pff, pw2T, b2, pattn, out, D_MODEL, D_FF);
}